// round 9
// baseline (speedup 1.0000x reference)
#include <cuda_runtime.h>
#include <cstdint>

// ---------------- problem constants ----------------
#define MTOT 16384
#define KTOT 1024
#define NTOT 1024

#define TILE_BYTES 8192          /* one 128x64 int8 tile */
#define KT 16                    /* k-tiles per full K   */
#define MT 128                   /* m-tiles (persistent CTAs) */

#define THREADS 256
#define B_STAGES 4
#define B_STAGE_BYTES (2 * TILE_BYTES)            /* 16 KB: 256 n-rows x 64 k */
#define A_SMEM_BYTES (KT * TILE_BYTES)            /* 128 KB persistent A      */
#define SMEM_TOTAL (A_SMEM_BYTES + B_STAGES * B_STAGE_BYTES)  /* 192 KB */

#define NTS 4                    /* four 256-col output slabs */
#define GSTEPS (NTS * KT)        /* 64 flat pipeline steps    */

// ---------------- scratch (device globals; no allocation allowed) ----------------
__device__ __align__(16) unsigned char g_wb[(size_t)NTOT * KTOT];  // 1 MB int8, tiled+swizzled
__device__ float g_alpha[NTOT];
__device__ float g_beta[NTOT];

// Tile layout: [128 rows r][64 k-bytes] packed as 64 physical rows of 128B:
//   off(r, kc16) = (r>>1)*128 + ( (((r&1)<<6) | kc16) ^ (((r>>1)&7)<<4) )
// Conflict-free for ldmatrix address groups; linear 16B-chunk copy preserved.
__device__ __forceinline__ uint32_t tile_off(uint32_t r, uint32_t kc16) {
    uint32_t pr = r >> 1;
    return pr * 128u + (((((r & 1u) << 6) | kc16) ^ ((pr & 7u) << 4)));
}

// ---------------- PTX helpers (sm_80+ only; no 'a'-gated instructions) ----------------
__device__ __forceinline__ void cp16(uint32_t dst, const void* src) {
    asm volatile("cp.async.cg.shared.global [%0], [%1], 16;" :: "r"(dst), "l"(src));
}
__device__ __forceinline__ void cp_commit() {
    asm volatile("cp.async.commit_group;" ::: "memory");
}
__device__ __forceinline__ void cp_wait2() {
    asm volatile("cp.async.wait_group 2;" ::: "memory");
}
__device__ __forceinline__ void ldsm4(uint32_t& r0, uint32_t& r1, uint32_t& r2, uint32_t& r3,
                                      uint32_t addr) {
    asm volatile("ldmatrix.sync.aligned.m8n8.x4.shared.b16 {%0,%1,%2,%3}, [%4];"
                 : "=r"(r0), "=r"(r1), "=r"(r2), "=r"(r3) : "r"(addr));
}
__device__ __forceinline__ void mma_s8(int* c, const uint32_t* a, const uint32_t* b) {
    asm volatile(
        "mma.sync.aligned.m16n8k32.row.col.s32.s8.s8.s32 "
        "{%0,%1,%2,%3}, {%4,%5,%6,%7}, {%8,%9}, {%0,%1,%2,%3};"
        : "+r"(c[0]), "+r"(c[1]), "+r"(c[2]), "+r"(c[3])
        : "r"(a[0]), "r"(a[1]), "r"(a[2]), "r"(a[3]), "r"(b[0]), "r"(b[1]));
}

__device__ __forceinline__ int q8(float v, float inv, float zp) {
    // match reference: round(x * (1/s) + zp), half-even, then clamp
    float t = __fadd_rn(__fmul_rn(v, inv), zp);
    return (int)fminf(fmaxf(rintf(t), -128.0f), 127.0f);
}
__device__ __forceinline__ uint32_t pack4(int a, int b, int c, int d) {
    return (uint32_t)(a & 255) | ((uint32_t)(b & 255) << 8) |
           ((uint32_t)(c & 255) << 16) | ((uint32_t)(d & 255) << 24);
}

// ---------------- kernel 1: weight prep -> tiled/swizzled int8 + alpha/beta ----------------
__global__ __launch_bounds__(64) void wprep_kernel(
    const int* __restrict__ w,
    const float* __restrict__ wscale,
    const float* __restrict__ act_scale,
    const float* __restrict__ act_zp,
    const float* __restrict__ bias)
{
    __shared__ int red[2];
    const int o = blockIdx.x, t = threadIdx.x;
    const int4* wr = reinterpret_cast<const int4*>(w + (size_t)o * KTOT + t * 16);
    int4 p0 = wr[0], p1 = wr[1], p2 = wr[2], p3 = wr[3];

    int sum = p0.x + p0.y + p0.z + p0.w + p1.x + p1.y + p1.z + p1.w
            + p2.x + p2.y + p2.z + p2.w + p3.x + p3.y + p3.z + p3.w;

    uint32_t pk[4];
    pk[0] = pack4(p0.x, p0.y, p0.z, p0.w);
    pk[1] = pack4(p1.x, p1.y, p1.z, p1.w);
    pk[2] = pack4(p2.x, p2.y, p2.z, p2.w);
    pk[3] = pack4(p3.x, p3.y, p3.z, p3.w);

    unsigned k0 = (unsigned)t << 4;
    unsigned ntile = (unsigned)o >> 7, nr = (unsigned)o & 127u;
    unsigned kt = k0 >> 6, kc = k0 & 63u;
    unsigned off = (ntile * 16u + kt) * TILE_BYTES + tile_off(nr, kc);
    *reinterpret_cast<uint4*>(g_wb + off) = *reinterpret_cast<uint4*>(pk);

#pragma unroll
    for (int d = 16; d > 0; d >>= 1) sum += __shfl_down_sync(0xffffffffu, sum, d);
    if ((t & 31) == 0) red[t >> 5] = sum;
    __syncthreads();
    if (t == 0) {
        int tot = red[0] + red[1];
        float alpha = wscale[o] * act_scale[0];
        g_alpha[o] = alpha;
        g_beta[o]  = bias[o] - act_zp[0] * (float)tot * alpha;
    }
}

// ---------------- kernel 2: persistent fused quant + int8 GEMM + dequant ----------------
// 128 CTAs (one per m-tile), 256 threads = 8 warps in 2(m) x 4(n), 1 CTA/SM.
// Phase 1: quantize own 128x1024 A slice straight into persistent smem (no gmem A).
// Phase 2: flat 64-step pipeline over (nts, kt); B streamed via 4-stage cp.async;
//          epilogue per 256-col slab fires in-loop (overlaps next-slab B prefetch).
__global__ __launch_bounds__(THREADS, 1) void gemm_kernel(
    float* __restrict__ out,
    const float* __restrict__ x,
    const float* __restrict__ act_scale,
    const float* __restrict__ act_zp)
{
    extern __shared__ __align__(128) unsigned char smem[];
    const uint32_t Sa = (uint32_t)__cvta_generic_to_shared(smem);
    const uint32_t Sb = Sa + A_SMEM_BYTES;

    const int tid = threadIdx.x, wid = tid >> 5, lid = tid & 31;
    const int wm = wid & 1, wn = wid >> 1;          // 2(m) x 4(n) warps
    const unsigned mt = blockIdx.x;

    // B stage copy for flat step g: nts = g>>4, kt = g&15; 16KB = 256 thr x 4 x 16B
#define ISSUE_B(g_)                                                               \
    do {                                                                          \
        const unsigned _g = (unsigned)(g_);                                       \
        const unsigned _nts = _g >> 4, _kt = _g & 15u;                            \
        const uint32_t _ds = Sb + (_g & 3u) * B_STAGE_BYTES;                      \
        _Pragma("unroll")                                                         \
        for (int j = 0; j < 4; j++) {                                             \
            unsigned c = (unsigned)tid + 256u * j;                                \
            unsigned tl = c >> 9, off = (c & 511u) * 16u;                         \
            cp16(_ds + c * 16u,                                                   \
                 g_wb + (((_nts * 2u + tl) * 16u + _kt) * TILE_BYTES) + off);     \
        }                                                                         \
    } while (0)

    // ---- issue first 3 B stages so their DRAM loads overlap the quant phase ----
#pragma unroll
    for (int p = 0; p < 3; p++) { ISSUE_B(p); cp_commit(); }

    // ---- phase 1: quantize this CTA's A slice into persistent smem ----
    {
        const float inv = 1.0f / act_scale[0];
        const float zp  = act_zp[0];
        const float* xrow = x + (size_t)mt * 128 * KTOT;
        for (int i = 0; i < 32; i++) {                  // 8192 chunks / 256 threads
            unsigned c = (unsigned)tid + 256u * i;
            unsigned r = c >> 6, ck = c & 63u;
            const float4* src = reinterpret_cast<const float4*>(xrow + r * KTOT + ck * 16u);
            uint32_t pk[4];
#pragma unroll
            for (int j = 0; j < 4; j++) {
                float4 v = src[j];
                pk[j] = pack4(q8(v.x, inv, zp), q8(v.y, inv, zp),
                              q8(v.z, inv, zp), q8(v.w, inv, zp));
            }
            unsigned kt = ck >> 2, kc = (ck & 3u) * 16u;
            *reinterpret_cast<uint4*>(smem + kt * TILE_BYTES + tile_off(r, kc)) =
                *reinterpret_cast<uint4*>(pk);
        }
    }
    __syncthreads();   // A visible to all warps before ldsm

    // ---- ldmatrix per-lane offsets ----
    uint32_t aoff[4][2], boff[4][2];
    {
        const uint32_t amr = (uint32_t)(wm * 64 + (lid & 15));
        const uint32_t akc = (uint32_t)((lid >> 4) * 16);
#pragma unroll
        for (int f = 0; f < 4; f++)
#pragma unroll
            for (int ks = 0; ks < 2; ks++)
                aoff[f][ks] = tile_off(amr + f * 16u, (uint32_t)(ks * 32) + akc);

        // warp wn covers local n rows [wn*64, wn*64+64) of the 256-row slab:
        // tile-local = (wn&1)*64 + lane pattern; tile select = wn>>1
        const uint32_t bnr = (uint32_t)((wn & 1) * 64 + (lid & 7) + ((lid >> 4) << 3));
        const uint32_t bkc = (uint32_t)(((lid >> 3) & 1) * 16);
        const uint32_t btl = (uint32_t)(wn >> 1) * TILE_BYTES;
#pragma unroll
        for (int gg = 0; gg < 4; gg++)
#pragma unroll
            for (int ks = 0; ks < 2; ks++)
                boff[gg][ks] = btl + tile_off(bnr + gg * 16u, (uint32_t)(ks * 32) + bkc);
    }

    int acc[4][8][4] = {};
    const int row = lid >> 2, colp = (lid & 3) << 1;

    // ---- phase 2: flat pipeline over 64 (nts, kt) steps ----
    for (int g = 0; g < GSTEPS; g++) {
        cp_wait2();
        __syncthreads();
        if (g + 3 < GSTEPS) ISSUE_B(g + 3);
        cp_commit();

        const int kt = g & 15;
        const uint32_t ba = Sa + (uint32_t)kt * TILE_BYTES;
        const uint32_t bb = Sb + (uint32_t)(g & 3) * B_STAGE_BYTES;

        uint32_t a[2][4][4], b[2][8][2];
#pragma unroll
        for (int ks = 0; ks < 2; ks++) {
#pragma unroll
            for (int f = 0; f < 4; f++)
                ldsm4(a[ks][f][0], a[ks][f][1], a[ks][f][2], a[ks][f][3], ba + aoff[f][ks]);
#pragma unroll
            for (int gg = 0; gg < 4; gg++)
                ldsm4(b[ks][2 * gg][0], b[ks][2 * gg][1],
                      b[ks][2 * gg + 1][0], b[ks][2 * gg + 1][1], bb + boff[gg][ks]);
        }
#pragma unroll
        for (int ks = 0; ks < 2; ks++)
#pragma unroll
            for (int f = 0; f < 4; f++)
#pragma unroll
                for (int gg = 0; gg < 8; gg++)
                    mma_s8(acc[f][gg], a[ks][f], b[ks][gg]);

        if (kt == 15) {
            // ---- epilogue for slab nts = g>>4 (overlaps next-slab B prefetch) ----
            const int nts = g >> 4;
            const int ncol0 = nts * 256 + wn * 64 + colp;
            float2 al[8], be[8];
#pragma unroll
            for (int q = 0; q < 8; q++) {
                al[q] = *reinterpret_cast<const float2*>(&g_alpha[ncol0 + q * 8]);
                be[q] = *reinterpret_cast<const float2*>(&g_beta[ncol0 + q * 8]);
            }
#pragma unroll
            for (int f = 0; f < 4; f++) {
                const size_t m0 = (size_t)(mt * 128 + wm * 64 + f * 16 + row);
                float* o0 = out + m0 * NTOT + ncol0;
                float* o1 = o0 + 8 * NTOT;
#pragma unroll
                for (int q = 0; q < 8; q++) {
                    float2 v0, v1;
                    v0.x = (float)acc[f][q][0] * al[q].x + be[q].x;
                    v0.y = (float)acc[f][q][1] * al[q].y + be[q].y;
                    v1.x = (float)acc[f][q][2] * al[q].x + be[q].x;
                    v1.y = (float)acc[f][q][3] * al[q].y + be[q].y;
                    *reinterpret_cast<float2*>(o0 + q * 8) = v0;
                    *reinterpret_cast<float2*>(o1 + q * 8) = v1;
                }
            }
            // reset accumulators for the next slab
#pragma unroll
            for (int f = 0; f < 4; f++)
#pragma unroll
                for (int q = 0; q < 8; q++)
#pragma unroll
                    for (int e = 0; e < 4; e++)
                        acc[f][q][e] = 0;
        }
    }
#undef ISSUE_B
}

// ---------------- launch ----------------
extern "C" void kernel_launch(void* const* d_in, const int* in_sizes, int n_in,
                              void* d_out, int out_size)
{
    const float* x      = (const float*)d_in[0];
    const int*   w      = (const int*)d_in[1];
    const float* wscale = (const float*)d_in[2];
    const float* ascale = (const float*)d_in[3];
    const float* azp    = (const float*)d_in[4];
    const float* bias   = (const float*)d_in[5];
    float* out = (float*)d_out;

    cudaFuncSetAttribute(gemm_kernel, cudaFuncAttributeMaxDynamicSharedMemorySize, SMEM_TOTAL);

    wprep_kernel<<<NTOT, 64>>>(w, wscale, ascale, azp, bias);
    gemm_kernel<<<MT, THREADS, SMEM_TOTAL>>>(out, x, ascale, azp);
}

// round 11
// speedup vs baseline: 1.3746x; 1.3746x over previous
#include <cuda_runtime.h>
#include <cstdint>

// ---------------- problem constants ----------------
#define MTOT 16384
#define KTOT 1024
#define NTOT 1024

#define BM 128
#define BN 128
#define KT 16             /* 64-byte k-tiles */
#define MT (MTOT / BM)    /* 128 m-tiles  */
#define NT (NTOT / BN)    /* 8 n-tiles    */

#define STAGES 4
#define TILE_BYTES (128 * 64)   /* 8192 */

#define QUANT_BLOCKS 4096
#define WPREP_BLOCKS 256        /* 4 output channels per 256-thread block */

// ---------------- scratch (device globals; no allocation allowed) ----------------
__device__ __align__(16) unsigned char g_xq[(size_t)MTOT * KTOT];  // 16 MB int8, tiled+swizzled
__device__ __align__(16) unsigned char g_wb[(size_t)NTOT * KTOT];  // 1 MB int8, tiled+swizzled
__device__ float g_alpha[NTOT];
__device__ float g_beta[NTOT];

// Tile layout: [128 rows r][64 k-bytes] packed as 64 physical rows of 128B:
//   off(r, kc16) = (r>>1)*128 + ( (((r&1)<<6) | kc16) ^ (((r>>1)&7)<<4) )
__device__ __forceinline__ uint32_t tile_off(uint32_t r, uint32_t kc16) {
    uint32_t pr = r >> 1;
    return pr * 128u + (((((r & 1u) << 6) | kc16) ^ ((pr & 7u) << 4)));
}

// ---------------- PTX helpers (sm_80+ only) ----------------
__device__ __forceinline__ void cp16(uint32_t dst, const void* src) {
    asm volatile("cp.async.cg.shared.global [%0], [%1], 16;" :: "r"(dst), "l"(src));
}
__device__ __forceinline__ void cp_commit() {
    asm volatile("cp.async.commit_group;" ::: "memory");
}
__device__ __forceinline__ void cp_wait2() {
    asm volatile("cp.async.wait_group 2;" ::: "memory");
}
__device__ __forceinline__ void ldsm4(uint32_t& r0, uint32_t& r1, uint32_t& r2, uint32_t& r3,
                                      uint32_t addr) {
    asm volatile("ldmatrix.sync.aligned.m8n8.x4.shared.b16 {%0,%1,%2,%3}, [%4];"
                 : "=r"(r0), "=r"(r1), "=r"(r2), "=r"(r3) : "r"(addr));
}
__device__ __forceinline__ void mma_s8(int* c, const uint32_t* a, const uint32_t* b) {
    asm volatile(
        "mma.sync.aligned.m16n8k32.row.col.s32.s8.s8.s32 "
        "{%0,%1,%2,%3}, {%4,%5,%6,%7}, {%8,%9}, {%0,%1,%2,%3};"
        : "+r"(c[0]), "+r"(c[1]), "+r"(c[2]), "+r"(c[3])
        : "r"(a[0]), "r"(a[1]), "r"(a[2]), "r"(a[3]), "r"(b[0]), "r"(b[1]));
}

__device__ __forceinline__ int q8(float v, float inv, float zp) {
    // match reference: round(x * (1/s) + zp), half-even, then clamp
    float t = __fadd_rn(__fmul_rn(v, inv), zp);
    return (int)fminf(fmaxf(rintf(t), -128.0f), 127.0f);
}
__device__ __forceinline__ uint32_t pack4(int a, int b, int c, int d) {
    return (uint32_t)(a & 255) | ((uint32_t)(b & 255) << 8) |
           ((uint32_t)(c & 255) << 16) | ((uint32_t)(d & 255) << 24);
}

// ---------------- kernel 1: fused quant (coalesced writes) + weight prep ----------------
// Blocks [0, 4096): quantize x. Thread g owns the g-th PHYSICAL 16B chunk of g_xq
// (perfectly coalesced 512B warp stores) and inverts the swizzle to find (m, k).
// Blocks [4096, 4352): weight prep, 4 output channels per block (64 threads each).
__global__ __launch_bounds__(256) void prep_kernel(
    const float* __restrict__ x,
    const float* __restrict__ act_scale,
    const float* __restrict__ act_zp,
    const int*   __restrict__ w,
    const float* __restrict__ wscale,
    const float* __restrict__ bias)
{
    const int tid = threadIdx.x;
    if (blockIdx.x < QUANT_BLOCKS) {
        // ---------- quant path ----------
        const float inv = 1.0f / act_scale[0];
        const float zp  = act_zp[0];
        unsigned g = blockIdx.x * 256u + tid;       // physical 16B chunk index
        unsigned tile = g >> 9;                      // 512 chunks per 8KB tile
        unsigned wo   = (g & 511u) << 4;             // within-tile byte offset
        unsigned pr   = wo >> 7;                     // physical row 0..63
        unsigned q16  = wo & 127u;                   // q*16, bits 4-6
        unsigned lc   = q16 ^ ((pr & 7u) << 4);      // deswizzled logical combo
        unsigned r    = (pr << 1) | (lc >> 6);       // logical row 0..127
        unsigned kc   = lc & 48u;                    // k-chunk byte offset {0,16,32,48}
        unsigned mt   = tile >> 4, kt = tile & 15u;
        unsigned m    = mt * 128u + r;
        unsigned k0   = kt * 64u + kc;               // k element index (int8 == element)

        const float4* src = reinterpret_cast<const float4*>(x + (size_t)m * KTOT + k0);
        uint32_t pk[4];
#pragma unroll
        for (int j = 0; j < 4; j++) {
            float4 v = src[j];
            pk[j] = pack4(q8(v.x, inv, zp), q8(v.y, inv, zp), q8(v.z, inv, zp), q8(v.w, inv, zp));
        }
        *reinterpret_cast<uint4*>(g_xq + (size_t)g * 16u) = *reinterpret_cast<uint4*>(pk);
    } else {
        // ---------- weight prep path ----------
        __shared__ int red[4][2];
        const int bid2 = blockIdx.x - QUANT_BLOCKS;       // 0..255
        const int s = tid >> 6, t = tid & 63;             // channel slot, lane-in-channel
        const int o = bid2 * 4 + s;

        const int4* wr = reinterpret_cast<const int4*>(w + (size_t)o * KTOT + t * 16);
        int4 p0 = wr[0], p1 = wr[1], p2 = wr[2], p3 = wr[3];

        int sum = p0.x + p0.y + p0.z + p0.w + p1.x + p1.y + p1.z + p1.w
                + p2.x + p2.y + p2.z + p2.w + p3.x + p3.y + p3.z + p3.w;

        uint32_t pk[4];
        pk[0] = pack4(p0.x, p0.y, p0.z, p0.w);
        pk[1] = pack4(p1.x, p1.y, p1.z, p1.w);
        pk[2] = pack4(p2.x, p2.y, p2.z, p2.w);
        pk[3] = pack4(p3.x, p3.y, p3.z, p3.w);

        unsigned k0 = (unsigned)t << 4;
        unsigned ntile = (unsigned)o >> 7, nr = (unsigned)o & 127u;
        unsigned kt = k0 >> 6, kc = k0 & 63u;
        unsigned off = (ntile * 16u + kt) * TILE_BYTES + tile_off(nr, kc);
        *reinterpret_cast<uint4*>(g_wb + off) = *reinterpret_cast<uint4*>(pk);

#pragma unroll
        for (int d = 16; d > 0; d >>= 1) sum += __shfl_down_sync(0xffffffffu, sum, d);
        if ((t & 31) == 0) red[s][t >> 5] = sum;
        __syncthreads();
        if (t == 0) {
            int tot = red[s][0] + red[s][1];
            float alpha = wscale[o] * act_scale[0];
            g_alpha[o] = alpha;
            g_beta[o]  = bias[o] - act_zp[0] * (float)tot * alpha;
        }
    }
}

// ---------------- kernel 2: int8 mma.sync GEMM + dequant epilogue (R6 proven core) ----------------
// 1024 CTAs (128 mt x 8 nt), 128 threads = 4 warps (2m x 2n), 2 CTAs/SM.
__global__ __launch_bounds__(128, 2) void gemm_kernel(float* __restrict__ out)
{
    extern __shared__ __align__(128) unsigned char smem[];
    const uint32_t Sa = (uint32_t)__cvta_generic_to_shared(smem);
    const uint32_t Sb = Sa + STAGES * TILE_BYTES;

    const int tid = threadIdx.x, wid = tid >> 5, lid = tid & 31;
    const int wm = wid & 1, wn = wid >> 1;
    const unsigned mt = blockIdx.x >> 3, nt = blockIdx.x & 7u;

    const unsigned char* ag = g_xq + (size_t)mt * KT * TILE_BYTES;
    const unsigned char* bg = g_wb + (size_t)nt * KT * TILE_BYTES;

    uint32_t aoff[4][2], boff[4][2];
    {
        const uint32_t amr = (uint32_t)(wm * 64 + (lid & 15));
        const uint32_t akc = (uint32_t)((lid >> 4) * 16);
#pragma unroll
        for (int f = 0; f < 4; f++)
#pragma unroll
            for (int ks = 0; ks < 2; ks++)
                aoff[f][ks] = tile_off(amr + f * 16u, (uint32_t)(ks * 32) + akc);

        const uint32_t bnr = (uint32_t)(wn * 64 + (lid & 7) + ((lid >> 4) << 3));
        const uint32_t bkc = (uint32_t)(((lid >> 3) & 1) * 16);
#pragma unroll
        for (int gg = 0; gg < 4; gg++)
#pragma unroll
            for (int ks = 0; ks < 2; ks++)
                boff[gg][ks] = tile_off(bnr + gg * 16u, (uint32_t)(ks * 32) + bkc);
    }

    int acc[4][8][4] = {};

#define ISSUE_COPY(st_, kt_)                                                      \
    do {                                                                          \
        uint32_t da = Sa + (uint32_t)(st_) * TILE_BYTES;                          \
        uint32_t db = Sb + (uint32_t)(st_) * TILE_BYTES;                          \
        const unsigned char* sa = ag + (size_t)(kt_) * TILE_BYTES;                \
        const unsigned char* sbp = bg + (size_t)(kt_) * TILE_BYTES;               \
        cp16(da + tid * 16,           sa + tid * 16);                             \
        cp16(da + (tid + 128) * 16,   sa + (tid + 128) * 16);                     \
        cp16(da + (tid + 256) * 16,   sa + (tid + 256) * 16);                     \
        cp16(da + (tid + 384) * 16,   sa + (tid + 384) * 16);                     \
        cp16(db + tid * 16,           sbp + tid * 16);                            \
        cp16(db + (tid + 128) * 16,   sbp + (tid + 128) * 16);                    \
        cp16(db + (tid + 256) * 16,   sbp + (tid + 256) * 16);                    \
        cp16(db + (tid + 384) * 16,   sbp + (tid + 384) * 16);                    \
    } while (0)

#pragma unroll
    for (int p = 0; p < STAGES - 1; p++) { ISSUE_COPY(p, p); cp_commit(); }

    for (int kt = 0; kt < KT; kt++) {
        cp_wait2();
        __syncthreads();
        const int nk = kt + STAGES - 1;
        if (nk < KT) ISSUE_COPY(nk & (STAGES - 1), nk);
        cp_commit();

        const uint32_t ba = Sa + (uint32_t)(kt & (STAGES - 1)) * TILE_BYTES;
        const uint32_t bb = Sb + (uint32_t)(kt & (STAGES - 1)) * TILE_BYTES;

        uint32_t a[2][4][4], b[2][8][2];
#pragma unroll
        for (int ks = 0; ks < 2; ks++) {
#pragma unroll
            for (int f = 0; f < 4; f++)
                ldsm4(a[ks][f][0], a[ks][f][1], a[ks][f][2], a[ks][f][3], ba + aoff[f][ks]);
#pragma unroll
            for (int gg = 0; gg < 4; gg++)
                ldsm4(b[ks][2 * gg][0], b[ks][2 * gg][1],
                      b[ks][2 * gg + 1][0], b[ks][2 * gg + 1][1], bb + boff[gg][ks]);
        }
#pragma unroll
        for (int ks = 0; ks < 2; ks++)
#pragma unroll
            for (int f = 0; f < 4; f++)
#pragma unroll
                for (int g = 0; g < 8; g++)
                    mma_s8(acc[f][g], a[ks][f], b[ks][g]);
    }

    const int row = lid >> 2, colp = (lid & 3) << 1;
    const int ncol0 = (int)(nt * 128) + wn * 64 + colp;

    float2 al[8], be[8];
#pragma unroll
    for (int g = 0; g < 8; g++) {
        al[g] = *reinterpret_cast<const float2*>(&g_alpha[ncol0 + g * 8]);
        be[g] = *reinterpret_cast<const float2*>(&g_beta[ncol0 + g * 8]);
    }

#pragma unroll
    for (int f = 0; f < 4; f++) {
        const size_t m0 = (size_t)(mt * 128 + wm * 64 + f * 16 + row);
        float* o0 = out + m0 * NTOT + ncol0;
        float* o1 = o0 + 8 * NTOT;
#pragma unroll
        for (int g = 0; g < 8; g++) {
            float2 v0, v1;
            v0.x = (float)acc[f][g][0] * al[g].x + be[g].x;
            v0.y = (float)acc[f][g][1] * al[g].y + be[g].y;
            v1.x = (float)acc[f][g][2] * al[g].x + be[g].x;
            v1.y = (float)acc[f][g][3] * al[g].y + be[g].y;
            *reinterpret_cast<float2*>(o0 + g * 8) = v0;
            *reinterpret_cast<float2*>(o1 + g * 8) = v1;
        }
    }
#undef ISSUE_COPY
}

// ---------------- launch ----------------
extern "C" void kernel_launch(void* const* d_in, const int* in_sizes, int n_in,
                              void* d_out, int out_size)
{
    const float* x      = (const float*)d_in[0];
    const int*   w      = (const int*)d_in[1];
    const float* wscale = (const float*)d_in[2];
    const float* ascale = (const float*)d_in[3];
    const float* azp    = (const float*)d_in[4];
    const float* bias   = (const float*)d_in[5];
    float* out = (float*)d_out;

    const int smem_bytes = 2 * STAGES * TILE_BYTES;   // 64 KB
    cudaFuncSetAttribute(gemm_kernel, cudaFuncAttributeMaxDynamicSharedMemorySize, smem_bytes);

    prep_kernel<<<QUANT_BLOCKS + WPREP_BLOCKS, 256>>>(x, ascale, azp, w, wscale, bias);
    gemm_kernel<<<MT * NT, 128, smem_bytes>>>(out);
}

// round 12
// speedup vs baseline: 1.4021x; 1.0200x over previous
#include <cuda_runtime.h>
#include <cstdint>

// ---------------- problem constants ----------------
#define MTOT 16384
#define KTOT 1024
#define NTOT 1024

#define BM 128
#define BN 128
#define KT 16             /* 64-byte k-tiles */
#define MT (MTOT / BM)    /* 128 m-tiles  */
#define NT (NTOT / BN)    /* 8 n-tiles    */

#define STAGES 4
#define TILE_BYTES (128 * 64)   /* 8192 */

#define QUANT_BLOCKS 4096
#define WPREP_BLOCKS 256        /* 4 output channels per 256-thread block */

// ---------------- scratch (device globals; no allocation allowed) ----------------
__device__ __align__(16) unsigned char g_xq[(size_t)MTOT * KTOT];  // 16 MB int8, tiled+swizzled
__device__ __align__(16) unsigned char g_wb[(size_t)NTOT * KTOT];  // 1 MB int8, tiled+swizzled
__device__ float g_alpha[NTOT];
__device__ float g_beta[NTOT];

// Tile layout: [128 rows r][64 k-bytes] packed as 64 physical rows of 128B:
//   off(r, kc16) = (r>>1)*128 + ( (((r&1)<<6) | kc16) ^ (((r>>1)&7)<<4) )
__device__ __forceinline__ uint32_t tile_off(uint32_t r, uint32_t kc16) {
    uint32_t pr = r >> 1;
    return pr * 128u + (((((r & 1u) << 6) | kc16) ^ ((pr & 7u) << 4)));
}

// ---------------- PTX helpers (sm_80+ only) ----------------
__device__ __forceinline__ void cp16(uint32_t dst, const void* src) {
    asm volatile("cp.async.cg.shared.global [%0], [%1], 16;" :: "r"(dst), "l"(src));
}
__device__ __forceinline__ void cp_commit() {
    asm volatile("cp.async.commit_group;" ::: "memory");
}
__device__ __forceinline__ void cp_wait2() {
    asm volatile("cp.async.wait_group 2;" ::: "memory");
}
__device__ __forceinline__ void ldsm4(uint32_t& r0, uint32_t& r1, uint32_t& r2, uint32_t& r3,
                                      uint32_t addr) {
    asm volatile("ldmatrix.sync.aligned.m8n8.x4.shared.b16 {%0,%1,%2,%3}, [%4];"
                 : "=r"(r0), "=r"(r1), "=r"(r2), "=r"(r3) : "r"(addr));
}
__device__ __forceinline__ void mma_s8(int* c, const uint32_t* a, const uint32_t* b) {
    asm volatile(
        "mma.sync.aligned.m16n8k32.row.col.s32.s8.s8.s32 "
        "{%0,%1,%2,%3}, {%4,%5,%6,%7}, {%8,%9}, {%0,%1,%2,%3};"
        : "+r"(c[0]), "+r"(c[1]), "+r"(c[2]), "+r"(c[3])
        : "r"(a[0]), "r"(a[1]), "r"(a[2]), "r"(a[3]), "r"(b[0]), "r"(b[1]));
}

__device__ __forceinline__ int q8(float v, float inv, float zp) {
    // match reference: round(x * (1/s) + zp), half-even, then clamp
    float t = __fadd_rn(__fmul_rn(v, inv), zp);
    return (int)fminf(fmaxf(rintf(t), -128.0f), 127.0f);
}
__device__ __forceinline__ uint32_t pack4(int a, int b, int c, int d) {
    return (uint32_t)(a & 255) | ((uint32_t)(b & 255) << 8) |
           ((uint32_t)(c & 255) << 16) | ((uint32_t)(d & 255) << 24);
}

// ---------------- kernel 1: fused quant (coalesced writes) + weight prep (R11 proven) ----------------
__global__ __launch_bounds__(256) void prep_kernel(
    const float* __restrict__ x,
    const float* __restrict__ act_scale,
    const float* __restrict__ act_zp,
    const int*   __restrict__ w,
    const float* __restrict__ wscale,
    const float* __restrict__ bias)
{
    const int tid = threadIdx.x;
    if (blockIdx.x < QUANT_BLOCKS) {
        const float inv = 1.0f / act_scale[0];
        const float zp  = act_zp[0];
        unsigned g = blockIdx.x * 256u + tid;       // physical 16B chunk index
        unsigned tile = g >> 9;
        unsigned wo   = (g & 511u) << 4;
        unsigned pr   = wo >> 7;
        unsigned q16  = wo & 127u;
        unsigned lc   = q16 ^ ((pr & 7u) << 4);
        unsigned r    = (pr << 1) | (lc >> 6);
        unsigned kc   = lc & 48u;
        unsigned mt   = tile >> 4, kt = tile & 15u;
        unsigned m    = mt * 128u + r;
        unsigned k0   = kt * 64u + kc;

        const float4* src = reinterpret_cast<const float4*>(x + (size_t)m * KTOT + k0);
        uint32_t pk[4];
#pragma unroll
        for (int j = 0; j < 4; j++) {
            float4 v = src[j];
            pk[j] = pack4(q8(v.x, inv, zp), q8(v.y, inv, zp), q8(v.z, inv, zp), q8(v.w, inv, zp));
        }
        *reinterpret_cast<uint4*>(g_xq + (size_t)g * 16u) = *reinterpret_cast<uint4*>(pk);
    } else {
        __shared__ int red[4][2];
        const int bid2 = blockIdx.x - QUANT_BLOCKS;
        const int s = tid >> 6, t = tid & 63;
        const int o = bid2 * 4 + s;

        const int4* wr = reinterpret_cast<const int4*>(w + (size_t)o * KTOT + t * 16);
        int4 p0 = wr[0], p1 = wr[1], p2 = wr[2], p3 = wr[3];

        int sum = p0.x + p0.y + p0.z + p0.w + p1.x + p1.y + p1.z + p1.w
                + p2.x + p2.y + p2.z + p2.w + p3.x + p3.y + p3.z + p3.w;

        uint32_t pk[4];
        pk[0] = pack4(p0.x, p0.y, p0.z, p0.w);
        pk[1] = pack4(p1.x, p1.y, p1.z, p1.w);
        pk[2] = pack4(p2.x, p2.y, p2.z, p2.w);
        pk[3] = pack4(p3.x, p3.y, p3.z, p3.w);

        unsigned k0 = (unsigned)t << 4;
        unsigned ntile = (unsigned)o >> 7, nr = (unsigned)o & 127u;
        unsigned kt = k0 >> 6, kc = k0 & 63u;
        unsigned off = (ntile * 16u + kt) * TILE_BYTES + tile_off(nr, kc);
        *reinterpret_cast<uint4*>(g_wb + off) = *reinterpret_cast<uint4*>(pk);

#pragma unroll
        for (int d = 16; d > 0; d >>= 1) sum += __shfl_down_sync(0xffffffffu, sum, d);
        if ((t & 31) == 0) red[s][t >> 5] = sum;
        __syncthreads();
        if (t == 0) {
            int tot = red[s][0] + red[s][1];
            float alpha = wscale[o] * act_scale[0];
            g_alpha[o] = alpha;
            g_beta[o]  = bias[o] - act_zp[0] * (float)tot * alpha;
        }
    }
}

// ---------------- kernel 2: int8 mma.sync GEMM, 16 warps/SM experiment ----------------
// 1024 CTAs (128 mt x 8 nt), 256 threads = 8 warps in 2(m) x 4(n), warp tile 64x32.
// 2 CTAs/SM -> 4 warps per SMSP feeding the tensor pipe (vs 2 before).
__global__ __launch_bounds__(256, 2) void gemm_kernel(float* __restrict__ out)
{
    extern __shared__ __align__(128) unsigned char smem[];
    const uint32_t Sa = (uint32_t)__cvta_generic_to_shared(smem);
    const uint32_t Sb = Sa + STAGES * TILE_BYTES;

    const int tid = threadIdx.x, wid = tid >> 5, lid = tid & 31;
    const int wm = wid & 1, wn = wid >> 1;       // 2(m) x 4(n)
    const unsigned mt = blockIdx.x >> 3, nt = blockIdx.x & 7u;

    const unsigned char* ag = g_xq + (size_t)mt * KT * TILE_BYTES;
    const unsigned char* bg = g_wb + (size_t)nt * KT * TILE_BYTES;

    // ldmatrix per-lane offsets
    uint32_t aoff[4][2], boff[2][2];
    {
        const uint32_t amr = (uint32_t)(wm * 64 + (lid & 15));
        const uint32_t akc = (uint32_t)((lid >> 4) * 16);
#pragma unroll
        for (int f = 0; f < 4; f++)
#pragma unroll
            for (int ks = 0; ks < 2; ks++)
                aoff[f][ks] = tile_off(amr + f * 16u, (uint32_t)(ks * 32) + akc);

        const uint32_t bnr = (uint32_t)(wn * 32 + (lid & 7) + ((lid >> 4) << 3));
        const uint32_t bkc = (uint32_t)(((lid >> 3) & 1) * 16);
#pragma unroll
        for (int gg = 0; gg < 2; gg++)
#pragma unroll
            for (int ks = 0; ks < 2; ks++)
                boff[gg][ks] = tile_off(bnr + gg * 16u, (uint32_t)(ks * 32) + bkc);
    }

    int acc[4][4][4] = {};

    // stage copy: 16KB = 256 threads x 4 x 16B (2 A chunks + 2 B chunks)
#define ISSUE_COPY(st_, kt_)                                                      \
    do {                                                                          \
        uint32_t da = Sa + (uint32_t)(st_) * TILE_BYTES;                          \
        uint32_t db = Sb + (uint32_t)(st_) * TILE_BYTES;                          \
        const unsigned char* sa = ag + (size_t)(kt_) * TILE_BYTES;                \
        const unsigned char* sbp = bg + (size_t)(kt_) * TILE_BYTES;               \
        cp16(da + tid * 16,           sa + tid * 16);                             \
        cp16(da + (tid + 256) * 16,   sa + (tid + 256) * 16);                     \
        cp16(db + tid * 16,           sbp + tid * 16);                            \
        cp16(db + (tid + 256) * 16,   sbp + (tid + 256) * 16);                    \
    } while (0)

#pragma unroll
    for (int p = 0; p < STAGES - 1; p++) { ISSUE_COPY(p, p); cp_commit(); }

    for (int kt = 0; kt < KT; kt++) {
        cp_wait2();
        __syncthreads();
        const int nk = kt + STAGES - 1;
        if (nk < KT) ISSUE_COPY(nk & (STAGES - 1), nk);
        cp_commit();

        const uint32_t ba = Sa + (uint32_t)(kt & (STAGES - 1)) * TILE_BYTES;
        const uint32_t bb = Sb + (uint32_t)(kt & (STAGES - 1)) * TILE_BYTES;

#pragma unroll
        for (int ks = 0; ks < 2; ks++) {
            uint32_t a[4][4], b[4][2];
#pragma unroll
            for (int f = 0; f < 4; f++)
                ldsm4(a[f][0], a[f][1], a[f][2], a[f][3], ba + aoff[f][ks]);
#pragma unroll
            for (int gg = 0; gg < 2; gg++)
                ldsm4(b[2 * gg][0], b[2 * gg][1], b[2 * gg + 1][0], b[2 * gg + 1][1],
                      bb + boff[gg][ks]);
#pragma unroll
            for (int f = 0; f < 4; f++)
#pragma unroll
                for (int g = 0; g < 4; g++)
                    mma_s8(acc[f][g], a[f], b[g]);
        }
    }

    // -------- epilogue: s32 -> float, *alpha + beta, float2 stores --------
    const int row = lid >> 2, colp = (lid & 3) << 1;
    const int ncol0 = (int)(nt * 128) + wn * 32 + colp;

    float2 al[4], be[4];
#pragma unroll
    for (int g = 0; g < 4; g++) {
        al[g] = *reinterpret_cast<const float2*>(&g_alpha[ncol0 + g * 8]);
        be[g] = *reinterpret_cast<const float2*>(&g_beta[ncol0 + g * 8]);
    }

#pragma unroll
    for (int f = 0; f < 4; f++) {
        const size_t m0 = (size_t)(mt * 128 + wm * 64 + f * 16 + row);
        float* o0 = out + m0 * NTOT + ncol0;
        float* o1 = o0 + 8 * NTOT;
#pragma unroll
        for (int g = 0; g < 4; g++) {
            float2 v0, v1;
            v0.x = (float)acc[f][g][0] * al[g].x + be[g].x;
            v0.y = (float)acc[f][g][1] * al[g].y + be[g].y;
            v1.x = (float)acc[f][g][2] * al[g].x + be[g].x;
            v1.y = (float)acc[f][g][3] * al[g].y + be[g].y;
            *reinterpret_cast<float2*>(o0 + g * 8) = v0;
            *reinterpret_cast<float2*>(o1 + g * 8) = v1;
        }
    }
#undef ISSUE_COPY
}

// ---------------- launch ----------------
extern "C" void kernel_launch(void* const* d_in, const int* in_sizes, int n_in,
                              void* d_out, int out_size)
{
    const float* x      = (const float*)d_in[0];
    const int*   w      = (const int*)d_in[1];
    const float* wscale = (const float*)d_in[2];
    const float* ascale = (const float*)d_in[3];
    const float* azp    = (const float*)d_in[4];
    const float* bias   = (const float*)d_in[5];
    float* out = (float*)d_out;

    const int smem_bytes = 2 * STAGES * TILE_BYTES;   // 64 KB
    cudaFuncSetAttribute(gemm_kernel, cudaFuncAttributeMaxDynamicSharedMemorySize, smem_bytes);

    prep_kernel<<<QUANT_BLOCKS + WPREP_BLOCKS, 256>>>(x, ascale, azp, w, wscale, bias);
    gemm_kernel<<<MT * NT, 256, smem_bytes>>>(out);
}